// round 1
// baseline (speedup 1.0000x reference)
#include <cuda_runtime.h>

#define GK   192
#define NPIX 65536

// scratch (allocation-free rule: __device__ globals)
__device__ float g_qkv[75497472];   // [2][576][65536]  302 MB
__device__ float g_att[25165824];   // [2][192][65536]  100 MB

// ---------------------------------------------------------------------------
// Generic 1x1-conv GEMM:  C[b,m,n] = sum_k A[m,k] * B[b,k,n]
// A: [M][192] (weights), B: [2][192][65536], C: [2][M][65536]
// Block tile 64(M) x 128(N), K-chunk 16, 256 threads, 4x8 per-thread microtile.
// ---------------------------------------------------------------------------
__global__ __launch_bounds__(256) void conv1x1_gemm(
    const float* __restrict__ A,
    const float* __restrict__ Bm,
    float* __restrict__ Cm,
    int M)
{
    const int bM = blockIdx.x * 64;
    const int bN = blockIdx.y * 128;
    const int batch = blockIdx.z;
    const float* B = Bm + (size_t)batch * GK * NPIX;
    float* C = Cm + (size_t)batch * M * NPIX;

    __shared__ float As[16][64];    // transposed: As[k][m]
    __shared__ float Bs[16][128];

    const int t  = threadIdx.x;
    const int tn = t & 15;          // n sub-tile (8 wide)
    const int tm = t >> 4;          // m sub-tile (4 tall)

    float acc[4][8];
    #pragma unroll
    for (int i = 0; i < 4; i++)
        #pragma unroll
        for (int j = 0; j < 8; j++) acc[i][j] = 0.f;

    for (int k0 = 0; k0 < GK; k0 += 16) {
        {   // A tile: 64 rows x 16 k, one float4 per thread, store transposed
            int row = t >> 2;
            int cg  = (t & 3) << 2;
            float4 a = *(const float4*)&A[(bM + row) * GK + k0 + cg];
            As[cg + 0][row] = a.x;
            As[cg + 1][row] = a.y;
            As[cg + 2][row] = a.z;
            As[cg + 3][row] = a.w;
        }
        {   // B tile: 16 k x 128 n, two float4 per thread, coalesced
            int row = t >> 5;
            int col = (t & 31) << 2;
            *(float4*)&Bs[row][col] =
                *(const float4*)&B[(size_t)(k0 + row) * NPIX + bN + col];
            *(float4*)&Bs[row + 8][col] =
                *(const float4*)&B[(size_t)(k0 + row + 8) * NPIX + bN + col];
        }
        __syncthreads();
        #pragma unroll
        for (int kk = 0; kk < 16; kk++) {
            float4 a  = *(const float4*)&As[kk][tm << 2];
            float4 b0 = *(const float4*)&Bs[kk][tn << 3];
            float4 b1 = *(const float4*)&Bs[kk][(tn << 3) + 4];
            float av[4] = {a.x, a.y, a.z, a.w};
            float bv[8] = {b0.x, b0.y, b0.z, b0.w, b1.x, b1.y, b1.z, b1.w};
            #pragma unroll
            for (int i = 0; i < 4; i++)
                #pragma unroll
                for (int j = 0; j < 8; j++)
                    acc[i][j] = fmaf(av[i], bv[j], acc[i][j]);
        }
        __syncthreads();
    }

    #pragma unroll
    for (int i = 0; i < 4; i++) {
        size_t off = (size_t)(bM + (tm << 2) + i) * NPIX + bN + (tn << 3);
        *(float4*)&C[off]     = make_float4(acc[i][0], acc[i][1], acc[i][2], acc[i][3]);
        *(float4*)&C[off + 4] = make_float4(acc[i][4], acc[i][5], acc[i][6], acc[i][7]);
    }
}

// ---------------------------------------------------------------------------
// Fused depthwise-3x3 + 8x8-window channel attention.
// One CTA per (window, head): 2048 windows * 4 heads = 8192 CTAs, 128 threads.
//   - loads 10x10 halo per 24-channel half, applies dw conv in smem
//   - q,k l2-normalized (norms folded into logits), softmax over 48 keys
//   - out = attn @ v written back in [b,c,h,w] layout for the proj GEMM
// ---------------------------------------------------------------------------
__global__ __launch_bounds__(128) void window_attn(
    const float* __restrict__ dww,    // [576*9]
    const float* __restrict__ tempr)  // [4]
{
    const int t    = threadIdx.x;
    const int head = blockIdx.x & 3;
    const int win  = blockIdx.x >> 2;
    const int b    = win >> 10;
    const int hn   = (win >> 5) & 31;
    const int wn   = win & 31;
    const int y0   = hn << 3, x0 = wn << 3;

    __shared__ float sq[48 * 64];        // q  [c][pix]
    __shared__ float skT[64 * 52];       // kT [pix][c]  (pad 52: conflict-free)
    __shared__ float sv[48 * 64];        // v  [c][pix]
    __shared__ float scratch[2400];      // halo temp [24][100]; later attn [48][49]
    __shared__ float qin[48], kin[48];

    const size_t qkv_base = (size_t)b * 576 * NPIX;

    // ---- depthwise conv into sq / skT / sv (two 24-channel halves each) ----
    for (int tensor = 0; tensor < 3; tensor++) {
        for (int half = 0; half < 2; half++) {
            const int gch0 = tensor * 192 + head * 48 + half * 24;
            for (int e = t; e < 2400; e += 128) {     // 24ch x 10x10 halo
                int c  = e / 100;
                int px = e - c * 100;
                int iy = px / 10;
                int ix = px - iy * 10;
                int gy = y0 - 1 + iy;
                int gx = x0 - 1 + ix;
                float v = 0.f;
                if ((unsigned)gy < 256u && (unsigned)gx < 256u)
                    v = g_qkv[qkv_base + (size_t)(gch0 + c) * NPIX + gy * 256 + gx];
                scratch[e] = v;
            }
            __syncthreads();
            for (int e = t; e < 1536; e += 128) {     // 24ch x 64 outputs
                int c  = e >> 6;
                int pp = e & 63;
                int p1 = pp >> 3, p2 = pp & 7;
                const float* wr = dww + (gch0 + c) * 9;
                const float* tp = scratch + c * 100 + p1 * 10 + p2;
                float s = tp[ 0]*wr[0] + tp[ 1]*wr[1] + tp[ 2]*wr[2]
                        + tp[10]*wr[3] + tp[11]*wr[4] + tp[12]*wr[5]
                        + tp[20]*wr[6] + tp[21]*wr[7] + tp[22]*wr[8];
                int ch = half * 24 + c;
                if      (tensor == 0) sq[ch * 64 + pp]  = s;
                else if (tensor == 1) skT[pp * 52 + ch] = s;
                else                  sv[ch * 64 + pp]  = s;
            }
            __syncthreads();
        }
    }

    // ---- l2 norms (folded into logits later) ----
    if (t < 48) {
        float s = 0.f;
        #pragma unroll 8
        for (int d = 0; d < 64; d++) {                // lane-rotated: no bank conflict
            float x = sq[t * 64 + ((d + t) & 63)];
            s = fmaf(x, x, s);
        }
        qin[t] = 1.f / fmaxf(sqrtf(s), 1e-12f);
    } else if (t >= 64 && t < 112) {
        int j = t - 64;
        float s = 0.f;
        #pragma unroll 8
        for (int d = 0; d < 64; d++) {
            float x = skT[d * 52 + j];
            s = fmaf(x, x, s);
        }
        kin[j] = 1.f / fmaxf(sqrtf(s), 1e-12f);
    }
    __syncthreads();

    float* sattn = scratch;                           // [48][49]
    const float tscale = __ldg(&tempr[head]);

    // ---- logits: attn[i][j] = <q_i, k_j> * qin*kin*T ; 6x3 register tile ----
    {
        const int ti = t >> 4;            // 0..7  -> i0 = 6*ti
        const int tj = t & 15;            // 0..15 -> j0 = 3*tj
        const int i0 = ti * 6, j0 = tj * 3;
        float acc[6][3];
        #pragma unroll
        for (int r = 0; r < 6; r++)
            #pragma unroll
            for (int s = 0; s < 3; s++) acc[r][s] = 0.f;

        for (int d0 = 0; d0 < 64; d0 += 4) {
            float4 qv[6];
            #pragma unroll
            for (int r = 0; r < 6; r++)
                qv[r] = *(const float4*)&sq[(i0 + r) * 64 + d0];
            #pragma unroll
            for (int dd = 0; dd < 4; dd++) {
                float kv[3];
                #pragma unroll
                for (int s = 0; s < 3; s++) kv[s] = skT[(d0 + dd) * 52 + j0 + s];
                #pragma unroll
                for (int r = 0; r < 6; r++) {
                    float qd = (dd == 0) ? qv[r].x : (dd == 1) ? qv[r].y
                             : (dd == 2) ? qv[r].z : qv[r].w;
                    #pragma unroll
                    for (int s = 0; s < 3; s++)
                        acc[r][s] = fmaf(qd, kv[s], acc[r][s]);
                }
            }
        }
        #pragma unroll
        for (int r = 0; r < 6; r++) {
            float qi = qin[i0 + r] * tscale;
            #pragma unroll
            for (int s = 0; s < 3; s++)
                sattn[(i0 + r) * 49 + j0 + s] = acc[r][s] * qi * kin[j0 + s];
        }
    }
    __syncthreads();

    // ---- softmax over j (one thread per row; 49-stride = conflict-free) ----
    if (t < 48) {
        float m = -1e30f;
        #pragma unroll 8
        for (int j = 0; j < 48; j++) m = fmaxf(m, sattn[t * 49 + j]);
        float s = 0.f;
        #pragma unroll 8
        for (int j = 0; j < 48; j++) {
            float e = __expf(sattn[t * 49 + j] - m);
            sattn[t * 49 + j] = e;
            s += e;
        }
        float inv = 1.f / s;
        #pragma unroll 8
        for (int j = 0; j < 48; j++) sattn[t * 49 + j] *= inv;
    }
    __syncthreads();

    // ---- out = attn @ v ; 6(i) x 4(d) register tile, write to g_att ----
    {
        const int td = t & 15;            // d0 = 4*td
        const int ti = t >> 4;            // i0 = 6*ti
        const int d0 = td * 4, i0 = ti * 6;
        float acc[6][4];
        #pragma unroll
        for (int r = 0; r < 6; r++)
            #pragma unroll
            for (int s = 0; s < 4; s++) acc[r][s] = 0.f;

        for (int j = 0; j < 48; j++) {
            float4 vv = *(const float4*)&sv[j * 64 + d0];
            #pragma unroll
            for (int r = 0; r < 6; r++) {
                float a = sattn[(i0 + r) * 49 + j];
                acc[r][0] = fmaf(a, vv.x, acc[r][0]);
                acc[r][1] = fmaf(a, vv.y, acc[r][1]);
                acc[r][2] = fmaf(a, vv.z, acc[r][2]);
                acc[r][3] = fmaf(a, vv.w, acc[r][3]);
            }
        }
        const int p1 = d0 >> 3, p2 = d0 & 7;
        const size_t obase = (size_t)b * 192 * NPIX
                           + (size_t)(y0 + p1) * 256 + (x0 + p2);
        #pragma unroll
        for (int r = 0; r < 6; r++) {
            size_t off = obase + (size_t)(head * 48 + i0 + r) * NPIX;
            *(float4*)&g_att[off] = make_float4(acc[r][0], acc[r][1], acc[r][2], acc[r][3]);
        }
    }
}

// ---------------------------------------------------------------------------
extern "C" void kernel_launch(void* const* d_in, const int* in_sizes, int n_in,
                              void* d_out, int out_size)
{
    const float *x = nullptr, *qw = nullptr, *dw = nullptr, *pw = nullptr, *tp = nullptr;
    for (int i = 0; i < n_in; i++) {
        switch (in_sizes[i]) {
            case 25165824: x  = (const float*)d_in[i]; break;  // x [2,192,256,256]
            case 110592:   qw = (const float*)d_in[i]; break;  // qkv_w [576,192]
            case 5184:     dw = (const float*)d_in[i]; break;  // dw_w [576,1,3,3]
            case 36864:    pw = (const float*)d_in[i]; break;  // proj_w [192,192]
            case 4:        tp = (const float*)d_in[i]; break;  // temperature [4]
        }
    }

    void *qkvp = nullptr, *attp = nullptr;
    cudaGetSymbolAddress(&qkvp, g_qkv);
    cudaGetSymbolAddress(&attp, g_att);

    // 1) qkv 1x1 conv: [576,192] x [192,65536] per batch
    dim3 g1(576 / 64, NPIX / 128, 2);
    conv1x1_gemm<<<g1, 256>>>(qw, x, (float*)qkvp, 576);

    // 2) fused depthwise 3x3 + windowed channel attention
    window_attn<<<8192, 128>>>(dw, tp);

    // 3) proj 1x1 conv: [192,192] x [192,65536] per batch -> d_out
    dim3 g3(192 / 64, NPIX / 128, 2);
    conv1x1_gemm<<<g3, 256>>>(pw, (const float*)attp, (float*)d_out, 192);
}

// round 2
// speedup vs baseline: 1.3915x; 1.3915x over previous
#include <cuda_runtime.h>

#define GK   192
#define NPIX 65536

// scratch (allocation-free rule: __device__ globals)
__device__ float g_qkv[75497472];   // [2][576][65536]  302 MB
__device__ float g_att[25165824];   // [2][192][65536]  100 MB

// ---------------------------------------------------------------------------
// 1x1-conv GEMM:  C[b,m,n] = sum_k A[m,k] * B[b,k,n]
// Block tile 64(M) x 128(N), K-chunk 16, 128 threads, 8x8 microtile,
// double-buffered smem. 4 LDS.128 per 64 FMA -> FMA-bound, not LDS-bound.
// ---------------------------------------------------------------------------
__global__ __launch_bounds__(128) void conv1x1_gemm(
    const float* __restrict__ A,
    const float* __restrict__ Bm,
    float* __restrict__ Cm,
    int M)
{
    const int bM = blockIdx.x * 64;
    const int bN = blockIdx.y * 128;
    const float* B = Bm + (size_t)blockIdx.z * GK * NPIX;
    float* C = Cm + (size_t)blockIdx.z * (size_t)M * NPIX;

    __shared__ float As[2][16][64];    // [k][m] transposed
    __shared__ float Bs[2][16][128];   // [k][n]

    const int t  = threadIdx.x;
    const int tm = t >> 4;             // 0..7   -> m frags at tm*4, tm*4+32
    const int tn = t & 15;             // 0..15  -> n frags at tn*4, tn*4+64

    // global->smem load mapping
    const int ar = t >> 1;             // 0..63  A row
    const int ac = (t & 1) << 3;       // 0 or 8 A col group
    const int br = t >> 3;             // 0..15  B row
    const int bc = (t & 7) << 2;       // 0..28  B col group

    float acc[8][8];
    #pragma unroll
    for (int i = 0; i < 8; i++)
        #pragma unroll
        for (int j = 0; j < 8; j++) acc[i][j] = 0.f;

    const float* Ar = &A[(bM + ar) * GK + ac];
    const float* Br = &B[(size_t)br * NPIX + bN + bc];

    // ---- prologue: load chunk 0 into buffer 0 ----
    {
        float4 a0 = *(const float4*)&Ar[0];
        float4 a1 = *(const float4*)&Ar[4];
        As[0][ac + 0][ar] = a0.x; As[0][ac + 1][ar] = a0.y;
        As[0][ac + 2][ar] = a0.z; As[0][ac + 3][ar] = a0.w;
        As[0][ac + 4][ar] = a1.x; As[0][ac + 5][ar] = a1.y;
        As[0][ac + 6][ar] = a1.z; As[0][ac + 7][ar] = a1.w;
        #pragma unroll
        for (int g = 0; g < 4; g++)
            *(float4*)&Bs[0][br][bc + g * 32] = *(const float4*)&Br[g * 32];
    }
    __syncthreads();

    #pragma unroll 1
    for (int c = 0; c < GK / 16; c++) {
        const int cur = c & 1;
        // prefetch next chunk into the other buffer (overlaps with FMAs)
        if (c + 1 < GK / 16) {
            const int nxt = cur ^ 1;
            const int k0 = (c + 1) * 16;
            float4 a0 = *(const float4*)&Ar[k0];
            float4 a1 = *(const float4*)&Ar[k0 + 4];
            As[nxt][ac + 0][ar] = a0.x; As[nxt][ac + 1][ar] = a0.y;
            As[nxt][ac + 2][ar] = a0.z; As[nxt][ac + 3][ar] = a0.w;
            As[nxt][ac + 4][ar] = a1.x; As[nxt][ac + 5][ar] = a1.y;
            As[nxt][ac + 6][ar] = a1.z; As[nxt][ac + 7][ar] = a1.w;
            #pragma unroll
            for (int g = 0; g < 4; g++)
                *(float4*)&Bs[nxt][br][bc + g * 32] =
                    *(const float4*)&Br[(size_t)k0 * NPIX + g * 32];
        }
        #pragma unroll
        for (int kk = 0; kk < 16; kk++) {
            float4 a0 = *(const float4*)&As[cur][kk][tm * 4];
            float4 a1 = *(const float4*)&As[cur][kk][tm * 4 + 32];
            float4 b0 = *(const float4*)&Bs[cur][kk][tn * 4];
            float4 b1 = *(const float4*)&Bs[cur][kk][tn * 4 + 64];
            float av[8] = {a0.x, a0.y, a0.z, a0.w, a1.x, a1.y, a1.z, a1.w};
            float bv[8] = {b0.x, b0.y, b0.z, b0.w, b1.x, b1.y, b1.z, b1.w};
            #pragma unroll
            for (int i = 0; i < 8; i++)
                #pragma unroll
                for (int j = 0; j < 8; j++)
                    acc[i][j] = fmaf(av[i], bv[j], acc[i][j]);
        }
        __syncthreads();
    }

    // ---- epilogue ----
    #pragma unroll
    for (int half = 0; half < 2; half++) {
        #pragma unroll
        for (int i = 0; i < 4; i++) {
            const int m = bM + tm * 4 + half * 32 + i;
            size_t off = (size_t)m * NPIX + bN + tn * 4;
            float* a = acc[half * 4 + i];
            *(float4*)&C[off]      = make_float4(a[0], a[1], a[2], a[3]);
            *(float4*)&C[off + 64] = make_float4(a[4], a[5], a[6], a[7]);
        }
    }
}

// ---------------------------------------------------------------------------
// Fused depthwise-3x3 + 8x8-window channel attention (unchanged from R1).
// One CTA per (window, head): 8192 CTAs, 128 threads.
// ---------------------------------------------------------------------------
__global__ __launch_bounds__(128) void window_attn(
    const float* __restrict__ dww,    // [576*9]
    const float* __restrict__ tempr)  // [4]
{
    const int t    = threadIdx.x;
    const int head = blockIdx.x & 3;
    const int win  = blockIdx.x >> 2;
    const int b    = win >> 10;
    const int hn   = (win >> 5) & 31;
    const int wn   = win & 31;
    const int y0   = hn << 3, x0 = wn << 3;

    __shared__ float sq[48 * 64];        // q  [c][pix]
    __shared__ float skT[64 * 52];       // kT [pix][c]  (pad 52: conflict-free)
    __shared__ float sv[48 * 64];        // v  [c][pix]
    __shared__ float scratch[2400];      // halo temp [24][100]; later attn [48][49]
    __shared__ float qin[48], kin[48];

    const size_t qkv_base = (size_t)b * 576 * NPIX;

    // ---- depthwise conv into sq / skT / sv (two 24-channel halves each) ----
    for (int tensor = 0; tensor < 3; tensor++) {
        for (int half = 0; half < 2; half++) {
            const int gch0 = tensor * 192 + head * 48 + half * 24;
            for (int e = t; e < 2400; e += 128) {     // 24ch x 10x10 halo
                int c  = e / 100;
                int px = e - c * 100;
                int iy = px / 10;
                int ix = px - iy * 10;
                int gy = y0 - 1 + iy;
                int gx = x0 - 1 + ix;
                float v = 0.f;
                if ((unsigned)gy < 256u && (unsigned)gx < 256u)
                    v = g_qkv[qkv_base + (size_t)(gch0 + c) * NPIX + gy * 256 + gx];
                scratch[e] = v;
            }
            __syncthreads();
            for (int e = t; e < 1536; e += 128) {     // 24ch x 64 outputs
                int c  = e >> 6;
                int pp = e & 63;
                int p1 = pp >> 3, p2 = pp & 7;
                const float* wr = dww + (gch0 + c) * 9;
                const float* tp = scratch + c * 100 + p1 * 10 + p2;
                float s = tp[ 0]*wr[0] + tp[ 1]*wr[1] + tp[ 2]*wr[2]
                        + tp[10]*wr[3] + tp[11]*wr[4] + tp[12]*wr[5]
                        + tp[20]*wr[6] + tp[21]*wr[7] + tp[22]*wr[8];
                int ch = half * 24 + c;
                if      (tensor == 0) sq[ch * 64 + pp]  = s;
                else if (tensor == 1) skT[pp * 52 + ch] = s;
                else                  sv[ch * 64 + pp]  = s;
            }
            __syncthreads();
        }
    }

    // ---- l2 norms (folded into logits later) ----
    if (t < 48) {
        float s = 0.f;
        #pragma unroll 8
        for (int d = 0; d < 64; d++) {                // lane-rotated: no bank conflict
            float x = sq[t * 64 + ((d + t) & 63)];
            s = fmaf(x, x, s);
        }
        qin[t] = 1.f / fmaxf(sqrtf(s), 1e-12f);
    } else if (t >= 64 && t < 112) {
        int j = t - 64;
        float s = 0.f;
        #pragma unroll 8
        for (int d = 0; d < 64; d++) {
            float x = skT[d * 52 + j];
            s = fmaf(x, x, s);
        }
        kin[j] = 1.f / fmaxf(sqrtf(s), 1e-12f);
    }
    __syncthreads();

    float* sattn = scratch;                           // [48][49]
    const float tscale = __ldg(&tempr[head]);

    // ---- logits: attn[i][j] = <q_i, k_j> * qin*kin*T ; 6x3 register tile ----
    {
        const int ti = t >> 4;            // 0..7  -> i0 = 6*ti
        const int tj = t & 15;            // 0..15 -> j0 = 3*tj
        const int i0 = ti * 6, j0 = tj * 3;
        float acc[6][3];
        #pragma unroll
        for (int r = 0; r < 6; r++)
            #pragma unroll
            for (int s = 0; s < 3; s++) acc[r][s] = 0.f;

        for (int d0 = 0; d0 < 64; d0 += 4) {
            float4 qv[6];
            #pragma unroll
            for (int r = 0; r < 6; r++)
                qv[r] = *(const float4*)&sq[(i0 + r) * 64 + d0];
            #pragma unroll
            for (int dd = 0; dd < 4; dd++) {
                float kv[3];
                #pragma unroll
                for (int s = 0; s < 3; s++) kv[s] = skT[(d0 + dd) * 52 + j0 + s];
                #pragma unroll
                for (int r = 0; r < 6; r++) {
                    float qd = (dd == 0) ? qv[r].x : (dd == 1) ? qv[r].y
                             : (dd == 2) ? qv[r].z : qv[r].w;
                    #pragma unroll
                    for (int s = 0; s < 3; s++)
                        acc[r][s] = fmaf(qd, kv[s], acc[r][s]);
                }
            }
        }
        #pragma unroll
        for (int r = 0; r < 6; r++) {
            float qi = qin[i0 + r] * tscale;
            #pragma unroll
            for (int s = 0; s < 3; s++)
                sattn[(i0 + r) * 49 + j0 + s] = acc[r][s] * qi * kin[j0 + s];
        }
    }
    __syncthreads();

    // ---- softmax over j (one thread per row; 49-stride = conflict-free) ----
    if (t < 48) {
        float m = -1e30f;
        #pragma unroll 8
        for (int j = 0; j < 48; j++) m = fmaxf(m, sattn[t * 49 + j]);
        float s = 0.f;
        #pragma unroll 8
        for (int j = 0; j < 48; j++) {
            float e = __expf(sattn[t * 49 + j] - m);
            sattn[t * 49 + j] = e;
            s += e;
        }
        float inv = 1.f / s;
        #pragma unroll 8
        for (int j = 0; j < 48; j++) sattn[t * 49 + j] *= inv;
    }
    __syncthreads();

    // ---- out = attn @ v ; 6(i) x 4(d) register tile, write to g_att ----
    {
        const int td = t & 15;            // d0 = 4*td
        const int ti = t >> 4;            // i0 = 6*ti
        const int d0 = td * 4, i0 = ti * 6;
        float acc[6][4];
        #pragma unroll
        for (int r = 0; r < 6; r++)
            #pragma unroll
            for (int s = 0; s < 4; s++) acc[r][s] = 0.f;

        for (int j = 0; j < 48; j++) {
            float4 vv = *(const float4*)&sv[j * 64 + d0];
            #pragma unroll
            for (int r = 0; r < 6; r++) {
                float a = sattn[(i0 + r) * 49 + j];
                acc[r][0] = fmaf(a, vv.x, acc[r][0]);
                acc[r][1] = fmaf(a, vv.y, acc[r][1]);
                acc[r][2] = fmaf(a, vv.z, acc[r][2]);
                acc[r][3] = fmaf(a, vv.w, acc[r][3]);
            }
        }
        const int p1 = d0 >> 3, p2 = d0 & 7;
        const size_t obase = (size_t)b * 192 * NPIX
                           + (size_t)(y0 + p1) * 256 + (x0 + p2);
        #pragma unroll
        for (int r = 0; r < 6; r++) {
            size_t off = obase + (size_t)(head * 48 + i0 + r) * NPIX;
            *(float4*)&g_att[off] = make_float4(acc[r][0], acc[r][1], acc[r][2], acc[r][3]);
        }
    }
}

// ---------------------------------------------------------------------------
extern "C" void kernel_launch(void* const* d_in, const int* in_sizes, int n_in,
                              void* d_out, int out_size)
{
    const float *x = nullptr, *qw = nullptr, *dw = nullptr, *pw = nullptr, *tp = nullptr;
    for (int i = 0; i < n_in; i++) {
        switch (in_sizes[i]) {
            case 25165824: x  = (const float*)d_in[i]; break;  // x [2,192,256,256]
            case 110592:   qw = (const float*)d_in[i]; break;  // qkv_w [576,192]
            case 5184:     dw = (const float*)d_in[i]; break;  // dw_w [576,1,3,3]
            case 36864:    pw = (const float*)d_in[i]; break;  // proj_w [192,192]
            case 4:        tp = (const float*)d_in[i]; break;  // temperature [4]
        }
    }

    void *qkvp = nullptr, *attp = nullptr;
    cudaGetSymbolAddress(&qkvp, g_qkv);
    cudaGetSymbolAddress(&attp, g_att);

    // 1) qkv 1x1 conv: [576,192] x [192,65536] per batch
    dim3 g1(576 / 64, NPIX / 128, 2);
    conv1x1_gemm<<<g1, 128>>>(qw, x, (float*)qkvp, 576);

    // 2) fused depthwise 3x3 + windowed channel attention
    window_attn<<<8192, 128>>>(dw, tp);

    // 3) proj 1x1 conv: [192,192] x [192,65536] per batch -> d_out
    dim3 g3(192 / 64, NPIX / 128, 2);
    conv1x1_gemm<<<g3, 128>>>(pw, (const float*)attp, (float*)d_out, 192);
}

// round 3
// speedup vs baseline: 1.5355x; 1.1035x over previous
#include <cuda_runtime.h>

#define GK   192
#define NPIX 65536

// scratch (allocation-free rule: __device__ globals)
__device__ float g_qkv[75497472];   // [2][576][65536]  302 MB
__device__ float g_att[25165824];   // [2][192][65536]  100 MB

// packed fp32x2 FMA (Blackwell; only reachable via PTX)
#define FMA2(d, a, b) \
    asm("fma.rn.f32x2 %0, %1, %2, %3;" : "=l"(d) : "l"(a), "l"(b), "l"(d))

// ---------------------------------------------------------------------------
// 1x1-conv GEMM:  C[b,m,n] = sum_k A[m,k] * B[b,k,n]
// Block tile 64(M) x 128(N), K-chunk 16, 128 threads, 8x8 microtile,
// double-buffered smem, inner product in packed f32x2 (32 FFMA2 / 6 LDS.128).
// A stored duplicated {a,a} in smem so no packing MOVs are needed.
// ---------------------------------------------------------------------------
__global__ __launch_bounds__(128) void conv1x1_gemm(
    const float* __restrict__ A,
    const float* __restrict__ Bm,
    float* __restrict__ Cm,
    int M)
{
    const int bM = blockIdx.x * 64;
    const int bN = blockIdx.y * 128;
    const float* B = Bm + (size_t)blockIdx.z * GK * NPIX;
    float* C = Cm + (size_t)blockIdx.z * (size_t)M * NPIX;

    __shared__ __align__(16) float2 As2[2][16][64];   // [k][m] duplicated pairs
    __shared__ __align__(16) float  Bs[2][16][128];   // [k][n]

    const int t  = threadIdx.x;
    const int tm = t >> 4;             // 0..7   -> m frags at tm*4, tm*4+32
    const int tn = t & 15;             // 0..15  -> n frags at tn*4, tn*4+64

    // global->smem load mapping
    const int ar = t >> 1;             // 0..63  A row
    const int ac = (t & 1) << 3;       // 0 or 8 A col group
    const int br = t >> 3;             // 0..15  B row
    const int bc = (t & 7) << 2;       // 0..28  B col group

    unsigned long long acc2[8][4];     // [m][n-pair] packed f32x2 accumulators
    #pragma unroll
    for (int i = 0; i < 8; i++)
        #pragma unroll
        for (int j = 0; j < 4; j++) acc2[i][j] = 0ull;

    const float* Ar = &A[(bM + ar) * GK + ac];
    const float* Br = &B[(size_t)br * NPIX + bN + bc];

    // ---- prologue: load chunk 0 into buffer 0 ----
    {
        float4 a0 = *(const float4*)&Ar[0];
        float4 a1 = *(const float4*)&Ar[4];
        As2[0][ac + 0][ar] = make_float2(a0.x, a0.x);
        As2[0][ac + 1][ar] = make_float2(a0.y, a0.y);
        As2[0][ac + 2][ar] = make_float2(a0.z, a0.z);
        As2[0][ac + 3][ar] = make_float2(a0.w, a0.w);
        As2[0][ac + 4][ar] = make_float2(a1.x, a1.x);
        As2[0][ac + 5][ar] = make_float2(a1.y, a1.y);
        As2[0][ac + 6][ar] = make_float2(a1.z, a1.z);
        As2[0][ac + 7][ar] = make_float2(a1.w, a1.w);
        #pragma unroll
        for (int g = 0; g < 4; g++)
            *(float4*)&Bs[0][br][bc + g * 32] = *(const float4*)&Br[g * 32];
    }
    __syncthreads();

    #pragma unroll 1
    for (int c = 0; c < GK / 16; c++) {
        const int cur = c & 1;
        // prefetch next chunk into the other buffer (overlaps with FMAs)
        if (c + 1 < GK / 16) {
            const int nxt = cur ^ 1;
            const int k0 = (c + 1) * 16;
            float4 a0 = *(const float4*)&Ar[k0];
            float4 a1 = *(const float4*)&Ar[k0 + 4];
            As2[nxt][ac + 0][ar] = make_float2(a0.x, a0.x);
            As2[nxt][ac + 1][ar] = make_float2(a0.y, a0.y);
            As2[nxt][ac + 2][ar] = make_float2(a0.z, a0.z);
            As2[nxt][ac + 3][ar] = make_float2(a0.w, a0.w);
            As2[nxt][ac + 4][ar] = make_float2(a1.x, a1.x);
            As2[nxt][ac + 5][ar] = make_float2(a1.y, a1.y);
            As2[nxt][ac + 6][ar] = make_float2(a1.z, a1.z);
            As2[nxt][ac + 7][ar] = make_float2(a1.w, a1.w);
            #pragma unroll
            for (int g = 0; g < 4; g++)
                *(float4*)&Bs[nxt][br][bc + g * 32] =
                    *(const float4*)&Br[(size_t)k0 * NPIX + g * 32];
        }
        #pragma unroll
        for (int kk = 0; kk < 16; kk++) {
            const float2* ap0 = &As2[cur][kk][tm * 4];
            const float2* ap1 = &As2[cur][kk][tm * 4 + 32];
            ulonglong2 A0 = *(const ulonglong2*)ap0;
            ulonglong2 A1 = *(const ulonglong2*)(ap0 + 2);
            ulonglong2 A2 = *(const ulonglong2*)ap1;
            ulonglong2 A3 = *(const ulonglong2*)(ap1 + 2);
            ulonglong2 B0 = *(const ulonglong2*)&Bs[cur][kk][tn * 4];
            ulonglong2 B1 = *(const ulonglong2*)&Bs[cur][kk][tn * 4 + 64];
            unsigned long long av2[8] = {A0.x, A0.y, A1.x, A1.y,
                                         A2.x, A2.y, A3.x, A3.y};
            unsigned long long bv2[4] = {B0.x, B0.y, B1.x, B1.y};
            #pragma unroll
            for (int i = 0; i < 8; i++)
                #pragma unroll
                for (int j = 0; j < 4; j++)
                    FMA2(acc2[i][j], av2[i], bv2[j]);
        }
        __syncthreads();
    }

    // ---- epilogue: unpack f32x2 pairs and store ----
    #pragma unroll
    for (int half = 0; half < 2; half++) {
        #pragma unroll
        for (int i = 0; i < 4; i++) {
            const int m = bM + tm * 4 + half * 32 + i;
            size_t off = (size_t)m * NPIX + bN + tn * 4;
            unsigned long long* a = acc2[half * 4 + i];
            float2 f0 = *(float2*)&a[0];
            float2 f1 = *(float2*)&a[1];
            float2 f2 = *(float2*)&a[2];
            float2 f3 = *(float2*)&a[3];
            *(float4*)&C[off]      = make_float4(f0.x, f0.y, f1.x, f1.y);
            *(float4*)&C[off + 64] = make_float4(f2.x, f2.y, f3.x, f3.y);
        }
    }
}

// ---------------------------------------------------------------------------
// Fused depthwise-3x3 + 8x8-window channel attention.
// One CTA per (window, head): 8192 CTAs, 128 threads.
// Halo loads are fully unrolled (MLP=19) and software-pipelined across the
// six (tensor, half) phases so LDG latency hides behind the conv compute.
// ---------------------------------------------------------------------------
__global__ __launch_bounds__(128) void window_attn(
    const float* __restrict__ dww,    // [576*9]
    const float* __restrict__ tempr)  // [4]
{
    const int t    = threadIdx.x;
    const int head = blockIdx.x & 3;
    const int win  = blockIdx.x >> 2;
    const int b    = win >> 10;
    const int hn   = (win >> 5) & 31;
    const int wn   = win & 31;
    const int y0   = hn << 3, x0 = wn << 3;

    __shared__ float sq[48 * 64];        // q  [c][pix]
    __shared__ float skT[64 * 52];       // kT [pix][c]  (pad 52: conflict-free)
    __shared__ float sv[48 * 64];        // v  [c][pix]
    __shared__ float scratch[2400];      // halo temp [24][100]; later attn [48][49]
    __shared__ float qin[48], kin[48];

    const size_t qkv_base = (size_t)b * 576 * NPIX;

    // batched halo load: 24 ch x 10x10 pixels = 2400 elems, 19 regs/thread
    float hreg[19];
    auto load_halo = [&](int gch0) {
        #pragma unroll
        for (int i = 0; i < 19; i++) {
            int e = t + i * 128;
            float v = 0.f;
            if (e < 2400) {
                int c  = e / 100;
                int px = e - c * 100;
                int iy = px / 10;
                int ix = px - iy * 10;
                int gy = y0 - 1 + iy;
                int gx = x0 - 1 + ix;
                if ((unsigned)gy < 256u && (unsigned)gx < 256u)
                    v = g_qkv[qkv_base + (size_t)(gch0 + c) * NPIX + gy * 256 + gx];
            }
            hreg[i] = v;
        }
    };

    // ---- pipelined depthwise conv into sq / skT / sv ----
    load_halo(head * 48);                         // phase 0 (q, half 0)
    #pragma unroll 1
    for (int p = 0; p < 6; p++) {
        const int tensor = p >> 1;
        const int half   = p & 1;
        const int gch0   = tensor * 192 + head * 48 + half * 24;

        #pragma unroll
        for (int i = 0; i < 19; i++) {            // regs -> scratch
            int e = t + i * 128;
            if (e < 2400) scratch[e] = hreg[i];
        }
        __syncthreads();

        if (p < 6 - 1) {                          // prefetch next phase's halo
            const int np = p + 1;
            load_halo((np >> 1) * 192 + head * 48 + (np & 1) * 24);
        }

        #pragma unroll
        for (int u = 0; u < 12; u++) {            // 24ch x 64 outputs
            int e  = t + u * 128;
            int c  = e >> 6;
            int pp = e & 63;
            int p1 = pp >> 3, p2 = pp & 7;
            const float* wr = dww + (gch0 + c) * 9;
            const float* tp = scratch + c * 100 + p1 * 10 + p2;
            float s = tp[ 0]*wr[0] + tp[ 1]*wr[1] + tp[ 2]*wr[2]
                    + tp[10]*wr[3] + tp[11]*wr[4] + tp[12]*wr[5]
                    + tp[20]*wr[6] + tp[21]*wr[7] + tp[22]*wr[8];
            int ch = half * 24 + c;
            if      (tensor == 0) sq[ch * 64 + pp]  = s;
            else if (tensor == 1) skT[pp * 52 + ch] = s;
            else                  sv[ch * 64 + pp]  = s;
        }
        __syncthreads();
    }

    // ---- l2 norms (folded into logits later) ----
    if (t < 48) {
        float s = 0.f;
        #pragma unroll 8
        for (int d = 0; d < 64; d++) {                // lane-rotated: no bank conflict
            float x = sq[t * 64 + ((d + t) & 63)];
            s = fmaf(x, x, s);
        }
        qin[t] = 1.f / fmaxf(sqrtf(s), 1e-12f);
    } else if (t >= 64 && t < 112) {
        int j = t - 64;
        float s = 0.f;
        #pragma unroll 8
        for (int d = 0; d < 64; d++) {
            float x = skT[d * 52 + j];
            s = fmaf(x, x, s);
        }
        kin[j] = 1.f / fmaxf(sqrtf(s), 1e-12f);
    }
    __syncthreads();

    float* sattn = scratch;                           // [48][49]
    const float tscale = __ldg(&tempr[head]);

    // ---- logits: attn[i][j] = <q_i, k_j> * qin*kin*T ; 6x3 register tile ----
    {
        const int ti = t >> 4;            // 0..7  -> i0 = 6*ti
        const int tj = t & 15;            // 0..15 -> j0 = 3*tj
        const int i0 = ti * 6, j0 = tj * 3;
        float acc[6][3];
        #pragma unroll
        for (int r = 0; r < 6; r++)
            #pragma unroll
            for (int s = 0; s < 3; s++) acc[r][s] = 0.f;

        for (int d0 = 0; d0 < 64; d0 += 4) {
            float4 qv[6];
            #pragma unroll
            for (int r = 0; r < 6; r++)
                qv[r] = *(const float4*)&sq[(i0 + r) * 64 + d0];
            #pragma unroll
            for (int dd = 0; dd < 4; dd++) {
                float kv[3];
                #pragma unroll
                for (int s = 0; s < 3; s++) kv[s] = skT[(d0 + dd) * 52 + j0 + s];
                #pragma unroll
                for (int r = 0; r < 6; r++) {
                    float qd = (dd == 0) ? qv[r].x : (dd == 1) ? qv[r].y
                             : (dd == 2) ? qv[r].z : qv[r].w;
                    #pragma unroll
                    for (int s = 0; s < 3; s++)
                        acc[r][s] = fmaf(qd, kv[s], acc[r][s]);
                }
            }
        }
        #pragma unroll
        for (int r = 0; r < 6; r++) {
            float qi = qin[i0 + r] * tscale;
            #pragma unroll
            for (int s = 0; s < 3; s++)
                sattn[(i0 + r) * 49 + j0 + s] = acc[r][s] * qi * kin[j0 + s];
        }
    }
    __syncthreads();

    // ---- softmax over j (one thread per row; 49-stride = conflict-free) ----
    if (t < 48) {
        float m = -1e30f;
        #pragma unroll 8
        for (int j = 0; j < 48; j++) m = fmaxf(m, sattn[t * 49 + j]);
        float s = 0.f;
        #pragma unroll 8
        for (int j = 0; j < 48; j++) {
            float e = __expf(sattn[t * 49 + j] - m);
            sattn[t * 49 + j] = e;
            s += e;
        }
        float inv = 1.f / s;
        #pragma unroll 8
        for (int j = 0; j < 48; j++) sattn[t * 49 + j] *= inv;
    }
    __syncthreads();

    // ---- out = attn @ v ; 6(i) x 4(d) register tile, write to g_att ----
    {
        const int td = t & 15;            // d0 = 4*td
        const int ti = t >> 4;            // i0 = 6*ti
        const int d0 = td * 4, i0 = ti * 6;
        float acc[6][4];
        #pragma unroll
        for (int r = 0; r < 6; r++)
            #pragma unroll
            for (int s = 0; s < 4; s++) acc[r][s] = 0.f;

        for (int j = 0; j < 48; j++) {
            float4 vv = *(const float4*)&sv[j * 64 + d0];
            #pragma unroll
            for (int r = 0; r < 6; r++) {
                float a = sattn[(i0 + r) * 49 + j];
                acc[r][0] = fmaf(a, vv.x, acc[r][0]);
                acc[r][1] = fmaf(a, vv.y, acc[r][1]);
                acc[r][2] = fmaf(a, vv.z, acc[r][2]);
                acc[r][3] = fmaf(a, vv.w, acc[r][3]);
            }
        }
        const int p1 = d0 >> 3, p2 = d0 & 7;
        const size_t obase = (size_t)b * 192 * NPIX
                           + (size_t)(y0 + p1) * 256 + (x0 + p2);
        #pragma unroll
        for (int r = 0; r < 6; r++) {
            size_t off = obase + (size_t)(head * 48 + i0 + r) * NPIX;
            *(float4*)&g_att[off] = make_float4(acc[r][0], acc[r][1], acc[r][2], acc[r][3]);
        }
    }
}

// ---------------------------------------------------------------------------
extern "C" void kernel_launch(void* const* d_in, const int* in_sizes, int n_in,
                              void* d_out, int out_size)
{
    const float *x = nullptr, *qw = nullptr, *dw = nullptr, *pw = nullptr, *tp = nullptr;
    for (int i = 0; i < n_in; i++) {
        switch (in_sizes[i]) {
            case 25165824: x  = (const float*)d_in[i]; break;  // x [2,192,256,256]
            case 110592:   qw = (const float*)d_in[i]; break;  // qkv_w [576,192]
            case 5184:     dw = (const float*)d_in[i]; break;  // dw_w [576,1,3,3]
            case 36864:    pw = (const float*)d_in[i]; break;  // proj_w [192,192]
            case 4:        tp = (const float*)d_in[i]; break;  // temperature [4]
        }
    }

    void *qkvp = nullptr, *attp = nullptr;
    cudaGetSymbolAddress(&qkvp, g_qkv);
    cudaGetSymbolAddress(&attp, g_att);

    // 1) qkv 1x1 conv: [576,192] x [192,65536] per batch
    dim3 g1(576 / 64, NPIX / 128, 2);
    conv1x1_gemm<<<g1, 128>>>(qw, x, (float*)qkvp, 576);

    // 2) fused depthwise 3x3 + windowed channel attention
    window_attn<<<8192, 128>>>(dw, tp);

    // 3) proj 1x1 conv: [192,192] x [192,65536] per batch -> d_out
    dim3 g3(192 / 64, NPIX / 128, 2);
    conv1x1_gemm<<<g3, 128>>>(pw, (const float*)attp, (float*)d_out, 192);
}

// round 4
// speedup vs baseline: 1.6965x; 1.1049x over previous
#include <cuda_runtime.h>

#define GK   192
#define NPIX 65536

// scratch (allocation-free rule: __device__ globals)
__device__ float g_qkv[75497472];   // [2][576][65536]  302 MB
__device__ float g_att[25165824];   // [2][192][65536]  100 MB

// packed fp32x2 FMA (Blackwell; only reachable via PTX)
#define FMA2(d, a, b) \
    asm("fma.rn.f32x2 %0, %1, %2, %3;" : "=l"(d) : "l"(a), "l"(b), "l"(d))
// duplicate one f32 into both halves of a 64-bit register pair
#define PACK2(d, s) \
    asm("mov.b64 %0, {%1, %1};" : "=l"(d) : "f"(s))

// ---------------------------------------------------------------------------
// 1x1-conv GEMM:  C[b,m,n] = sum_k A[m,k] * B[b,k,n]
// Block tile 64(M) x 128(N), K-chunk 16, 128 threads, 8x8 microtile,
// double-buffered smem (R2 layout: 4 LDS.128 per k-step), inner product in
// packed f32x2: B pairs natural from LDS.128, A pairs built with reg movs.
// ---------------------------------------------------------------------------
__global__ __launch_bounds__(128) void conv1x1_gemm(
    const float* __restrict__ A,
    const float* __restrict__ Bm,
    float* __restrict__ Cm,
    int M)
{
    const int bM = blockIdx.x * 64;
    const int bN = blockIdx.y * 128;
    const float* B = Bm + (size_t)blockIdx.z * GK * NPIX;
    float* C = Cm + (size_t)blockIdx.z * (size_t)M * NPIX;

    __shared__ __align__(16) float As[2][16][64];    // [k][m] transposed
    __shared__ __align__(16) float Bs[2][16][128];   // [k][n]

    const int t  = threadIdx.x;
    const int tm = t >> 4;             // 0..7   -> m frags at tm*4, tm*4+32
    const int tn = t & 15;             // 0..15  -> n frags at tn*4, tn*4+64

    // global->smem load mapping
    const int ar = t >> 1;             // 0..63  A row
    const int ac = (t & 1) << 3;       // 0 or 8 A col group
    const int br = t >> 3;             // 0..15  B row
    const int bc = (t & 7) << 2;       // 0..28  B col group

    unsigned long long acc2[8][4];     // [m][n-pair] packed f32x2 accumulators
    #pragma unroll
    for (int i = 0; i < 8; i++)
        #pragma unroll
        for (int j = 0; j < 4; j++) acc2[i][j] = 0ull;

    const float* Ar = &A[(bM + ar) * GK + ac];
    const float* Br = &B[(size_t)br * NPIX + bN + bc];

    // ---- prologue: load chunk 0 into buffer 0 ----
    {
        float4 a0 = *(const float4*)&Ar[0];
        float4 a1 = *(const float4*)&Ar[4];
        As[0][ac + 0][ar] = a0.x; As[0][ac + 1][ar] = a0.y;
        As[0][ac + 2][ar] = a0.z; As[0][ac + 3][ar] = a0.w;
        As[0][ac + 4][ar] = a1.x; As[0][ac + 5][ar] = a1.y;
        As[0][ac + 6][ar] = a1.z; As[0][ac + 7][ar] = a1.w;
        #pragma unroll
        for (int g = 0; g < 4; g++)
            *(float4*)&Bs[0][br][bc + g * 32] = *(const float4*)&Br[g * 32];
    }
    __syncthreads();

    #pragma unroll 1
    for (int c = 0; c < GK / 16; c++) {
        const int cur = c & 1;
        // prefetch next chunk into the other buffer (overlaps with FMAs)
        if (c + 1 < GK / 16) {
            const int nxt = cur ^ 1;
            const int k0 = (c + 1) * 16;
            float4 a0 = *(const float4*)&Ar[k0];
            float4 a1 = *(const float4*)&Ar[k0 + 4];
            As[nxt][ac + 0][ar] = a0.x; As[nxt][ac + 1][ar] = a0.y;
            As[nxt][ac + 2][ar] = a0.z; As[nxt][ac + 3][ar] = a0.w;
            As[nxt][ac + 4][ar] = a1.x; As[nxt][ac + 5][ar] = a1.y;
            As[nxt][ac + 6][ar] = a1.z; As[nxt][ac + 7][ar] = a1.w;
            #pragma unroll
            for (int g = 0; g < 4; g++)
                *(float4*)&Bs[nxt][br][bc + g * 32] =
                    *(const float4*)&Br[(size_t)k0 * NPIX + g * 32];
        }
        #pragma unroll
        for (int kk = 0; kk < 16; kk++) {
            float4 a0 = *(const float4*)&As[cur][kk][tm * 4];
            float4 a1 = *(const float4*)&As[cur][kk][tm * 4 + 32];
            ulonglong2 B0 = *(const ulonglong2*)&Bs[cur][kk][tn * 4];
            ulonglong2 B1 = *(const ulonglong2*)&Bs[cur][kk][tn * 4 + 64];
            unsigned long long bv2[4] = {B0.x, B0.y, B1.x, B1.y};
            unsigned long long av2[8];
            PACK2(av2[0], a0.x); PACK2(av2[1], a0.y);
            PACK2(av2[2], a0.z); PACK2(av2[3], a0.w);
            PACK2(av2[4], a1.x); PACK2(av2[5], a1.y);
            PACK2(av2[6], a1.z); PACK2(av2[7], a1.w);
            #pragma unroll
            for (int i = 0; i < 8; i++)
                #pragma unroll
                for (int j = 0; j < 4; j++)
                    FMA2(acc2[i][j], av2[i], bv2[j]);
        }
        __syncthreads();
    }

    // ---- epilogue: unpack f32x2 pairs and store ----
    #pragma unroll
    for (int half = 0; half < 2; half++) {
        #pragma unroll
        for (int i = 0; i < 4; i++) {
            const int m = bM + tm * 4 + half * 32 + i;
            size_t off = (size_t)m * NPIX + bN + tn * 4;
            unsigned long long* a = acc2[half * 4 + i];
            float2 f0 = *(float2*)&a[0];
            float2 f1 = *(float2*)&a[1];
            float2 f2 = *(float2*)&a[2];
            float2 f3 = *(float2*)&a[3];
            *(float4*)&C[off]      = make_float4(f0.x, f0.y, f1.x, f1.y);
            *(float4*)&C[off + 64] = make_float4(f2.x, f2.y, f3.x, f3.y);
        }
    }
}

// ---------------------------------------------------------------------------
// Fused depthwise-3x3 + 8x8-window channel attention.
// One CTA per (window, head): 8192 CTAs, 256 threads (2x R3 for issue-width).
// Halo loads fully unrolled (MLP=10) and software-pipelined across phases.
// ---------------------------------------------------------------------------
__global__ __launch_bounds__(256) void window_attn(
    const float* __restrict__ dww,    // [576*9]
    const float* __restrict__ tempr)  // [4]
{
    const int t    = threadIdx.x;
    const int head = blockIdx.x & 3;
    const int win  = blockIdx.x >> 2;
    const int b    = win >> 10;
    const int hn   = (win >> 5) & 31;
    const int wn   = win & 31;
    const int y0   = hn << 3, x0 = wn << 3;

    __shared__ float sq[48 * 64];        // q  [c][pix]
    __shared__ float skT[64 * 52];       // kT [pix][c]  (pad 52: conflict-free)
    __shared__ float sv[48 * 64];        // v  [c][pix]
    __shared__ float scratch[2400];      // halo temp [24][100]; later attn [48][49]
    __shared__ float qin[48], kin[48];

    const size_t qkv_base = (size_t)b * 576 * NPIX;

    // batched halo load: 24 ch x 10x10 pixels = 2400 elems, 10 regs/thread
    float hreg[10];
    auto load_halo = [&](int gch0) {
        #pragma unroll
        for (int i = 0; i < 10; i++) {
            int e = t + i * 256;
            float v = 0.f;
            if (e < 2400) {
                int c  = e / 100;
                int px = e - c * 100;
                int iy = px / 10;
                int ix = px - iy * 10;
                int gy = y0 - 1 + iy;
                int gx = x0 - 1 + ix;
                if ((unsigned)gy < 256u && (unsigned)gx < 256u)
                    v = g_qkv[qkv_base + (size_t)(gch0 + c) * NPIX + gy * 256 + gx];
            }
            hreg[i] = v;
        }
    };

    // ---- pipelined depthwise conv into sq / skT / sv ----
    load_halo(head * 48);                         // phase 0 (q, half 0)
    #pragma unroll 1
    for (int p = 0; p < 6; p++) {
        const int tensor = p >> 1;
        const int half   = p & 1;
        const int gch0   = tensor * 192 + head * 48 + half * 24;

        #pragma unroll
        for (int i = 0; i < 10; i++) {            // regs -> scratch
            int e = t + i * 256;
            if (e < 2400) scratch[e] = hreg[i];
        }
        __syncthreads();

        if (p < 6 - 1) {                          // prefetch next phase's halo
            const int np = p + 1;
            load_halo((np >> 1) * 192 + head * 48 + (np & 1) * 24);
        }

        #pragma unroll
        for (int u = 0; u < 6; u++) {             // 24ch x 64 outputs
            int e  = t + u * 256;
            int c  = e >> 6;
            int pp = e & 63;
            int p1 = pp >> 3, p2 = pp & 7;
            const float* wr = dww + (gch0 + c) * 9;
            const float* tp = scratch + c * 100 + p1 * 10 + p2;
            float s = tp[ 0]*wr[0] + tp[ 1]*wr[1] + tp[ 2]*wr[2]
                    + tp[10]*wr[3] + tp[11]*wr[4] + tp[12]*wr[5]
                    + tp[20]*wr[6] + tp[21]*wr[7] + tp[22]*wr[8];
            int ch = half * 24 + c;
            if      (tensor == 0) sq[ch * 64 + pp]  = s;
            else if (tensor == 1) skT[pp * 52 + ch] = s;
            else                  sv[ch * 64 + pp]  = s;
        }
        __syncthreads();
    }

    // ---- l2 norms (folded into logits later) ----
    if (t < 48) {
        float s = 0.f;
        #pragma unroll 8
        for (int d = 0; d < 64; d++) {                // lane-rotated: no bank conflict
            float x = sq[t * 64 + ((d + t) & 63)];
            s = fmaf(x, x, s);
        }
        qin[t] = 1.f / fmaxf(sqrtf(s), 1e-12f);
    } else if (t >= 128 && t < 176) {
        int j = t - 128;
        float s = 0.f;
        #pragma unroll 8
        for (int d = 0; d < 64; d++) {
            float x = skT[d * 52 + j];
            s = fmaf(x, x, s);
        }
        kin[j] = 1.f / fmaxf(sqrtf(s), 1e-12f);
    }
    __syncthreads();

    float* sattn = scratch;                           // [48][49]
    const float tscale = __ldg(&tempr[head]);

    // ---- logits: attn[i][j] = <q_i, k_j> * qin*kin*T ; 3x3 register tile ----
    {
        const int ti = t >> 4;            // 0..15 -> i0 = 3*ti
        const int tj = t & 15;            // 0..15 -> j0 = 3*tj
        const int i0 = ti * 3, j0 = tj * 3;
        float acc[3][3];
        #pragma unroll
        for (int r = 0; r < 3; r++)
            #pragma unroll
            for (int s = 0; s < 3; s++) acc[r][s] = 0.f;

        for (int d0 = 0; d0 < 64; d0 += 4) {
            float4 qv[3];
            #pragma unroll
            for (int r = 0; r < 3; r++)
                qv[r] = *(const float4*)&sq[(i0 + r) * 64 + d0];
            #pragma unroll
            for (int dd = 0; dd < 4; dd++) {
                float kv[3];
                #pragma unroll
                for (int s = 0; s < 3; s++) kv[s] = skT[(d0 + dd) * 52 + j0 + s];
                #pragma unroll
                for (int r = 0; r < 3; r++) {
                    float qd = (dd == 0) ? qv[r].x : (dd == 1) ? qv[r].y
                             : (dd == 2) ? qv[r].z : qv[r].w;
                    #pragma unroll
                    for (int s = 0; s < 3; s++)
                        acc[r][s] = fmaf(qd, kv[s], acc[r][s]);
                }
            }
        }
        #pragma unroll
        for (int r = 0; r < 3; r++) {
            float qi = qin[i0 + r] * tscale;
            #pragma unroll
            for (int s = 0; s < 3; s++)
                sattn[(i0 + r) * 49 + j0 + s] = acc[r][s] * qi * kin[j0 + s];
        }
    }
    __syncthreads();

    // ---- softmax over j (one thread per row; 49-stride = conflict-free) ----
    if (t < 48) {
        float m = -1e30f;
        #pragma unroll 8
        for (int j = 0; j < 48; j++) m = fmaxf(m, sattn[t * 49 + j]);
        float s = 0.f;
        #pragma unroll 8
        for (int j = 0; j < 48; j++) {
            float e = __expf(sattn[t * 49 + j] - m);
            sattn[t * 49 + j] = e;
            s += e;
        }
        float inv = 1.f / s;
        #pragma unroll 8
        for (int j = 0; j < 48; j++) sattn[t * 49 + j] *= inv;
    }
    __syncthreads();

    // ---- out = attn @ v ; 3(i) x 4(d) register tile, write to g_att ----
    {
        const int td = t & 15;            // d0 = 4*td
        const int ti = t >> 4;            // i0 = 3*ti
        const int d0 = td * 4, i0 = ti * 3;
        float acc[3][4];
        #pragma unroll
        for (int r = 0; r < 3; r++)
            #pragma unroll
            for (int s = 0; s < 4; s++) acc[r][s] = 0.f;

        for (int j = 0; j < 48; j++) {
            float4 vv = *(const float4*)&sv[j * 64 + d0];
            #pragma unroll
            for (int r = 0; r < 3; r++) {
                float a = sattn[(i0 + r) * 49 + j];
                acc[r][0] = fmaf(a, vv.x, acc[r][0]);
                acc[r][1] = fmaf(a, vv.y, acc[r][1]);
                acc[r][2] = fmaf(a, vv.z, acc[r][2]);
                acc[r][3] = fmaf(a, vv.w, acc[r][3]);
            }
        }
        const int p1 = d0 >> 3, p2 = d0 & 7;
        const size_t obase = (size_t)b * 192 * NPIX
                           + (size_t)(y0 + p1) * 256 + (x0 + p2);
        #pragma unroll
        for (int r = 0; r < 3; r++) {
            size_t off = obase + (size_t)(head * 48 + i0 + r) * NPIX;
            *(float4*)&g_att[off] = make_float4(acc[r][0], acc[r][1], acc[r][2], acc[r][3]);
        }
    }
}

// ---------------------------------------------------------------------------
extern "C" void kernel_launch(void* const* d_in, const int* in_sizes, int n_in,
                              void* d_out, int out_size)
{
    const float *x = nullptr, *qw = nullptr, *dw = nullptr, *pw = nullptr, *tp = nullptr;
    for (int i = 0; i < n_in; i++) {
        switch (in_sizes[i]) {
            case 25165824: x  = (const float*)d_in[i]; break;  // x [2,192,256,256]
            case 110592:   qw = (const float*)d_in[i]; break;  // qkv_w [576,192]
            case 5184:     dw = (const float*)d_in[i]; break;  // dw_w [576,1,3,3]
            case 36864:    pw = (const float*)d_in[i]; break;  // proj_w [192,192]
            case 4:        tp = (const float*)d_in[i]; break;  // temperature [4]
        }
    }

    void *qkvp = nullptr, *attp = nullptr;
    cudaGetSymbolAddress(&qkvp, g_qkv);
    cudaGetSymbolAddress(&attp, g_att);

    // 1) qkv 1x1 conv: [576,192] x [192,65536] per batch
    dim3 g1(576 / 64, NPIX / 128, 2);
    conv1x1_gemm<<<g1, 128>>>(qw, x, (float*)qkvp, 576);

    // 2) fused depthwise 3x3 + windowed channel attention
    window_attn<<<8192, 256>>>(dw, tp);

    // 3) proj 1x1 conv: [192,192] x [192,65536] per batch -> d_out
    dim3 g3(192 / 64, NPIX / 128, 2);
    conv1x1_gemm<<<g3, 128>>>(pw, (const float*)attp, (float*)d_out, 192);
}

// round 6
// speedup vs baseline: 2.0376x; 1.2011x over previous
#include <cuda_runtime.h>
#include <cuda_bf16.h>
#include <cstdint>

#define GK   192
#define NPIX 65536

// ---------------------------------------------------------------------------
// scratch (allocation-free rule: __device__ globals)
// ---------------------------------------------------------------------------
__device__ float g_qkv[75497472];                         // [2][576][65536] f32
__device__ float g_att[25165824];                         // [2][192][65536] f32
__device__ __align__(16) unsigned short g_bth[25165824];  // [2][65536][192] bf16 hi
__device__ __align__(16) unsigned short g_btl[25165824];  // [2][65536][192] bf16 lo
__device__ __align__(16) unsigned short g_wqh[110592], g_wql[110592];
__device__ __align__(16) unsigned short g_wph[36864],  g_wpl[36864];

// ---------------------------------------------------------------------------
__device__ __forceinline__ uint32_t smem_u32(const void* p) {
    uint32_t a;
    asm("{ .reg .u64 t; cvta.to.shared.u64 t, %1; cvt.u32.u64 %0, t; }"
        : "=r"(a) : "l"(p));
    return a;
}

__device__ __forceinline__ void cp_async16(uint32_t dst, const void* src) {
    asm volatile("cp.async.cg.shared.global [%0], [%1], 16;"
                 :: "r"(dst), "l"(src) : "memory");
}

#define LDSM_X4(r0, r1, r2, r3, a) \
    asm volatile("ldmatrix.sync.aligned.m8n8.x4.shared.b16 {%0,%1,%2,%3}, [%4];" \
                 : "=r"(r0), "=r"(r1), "=r"(r2), "=r"(r3) : "r"(a))
#define LDSM_X2(r0, r1, a) \
    asm volatile("ldmatrix.sync.aligned.m8n8.x2.shared.b16 {%0,%1}, [%2];" \
                 : "=r"(r0), "=r"(r1) : "r"(a))

#define MMA16816(d, a, b) \
    asm volatile("mma.sync.aligned.m16n8k16.row.col.f32.bf16.bf16.f32 " \
                 "{%0,%1,%2,%3}, {%4,%5,%6,%7}, {%8,%9}, {%0,%1,%2,%3};" \
                 : "+f"((d)[0]), "+f"((d)[1]), "+f"((d)[2]), "+f"((d)[3]) \
                 : "r"((a)[0]), "r"((a)[1]), "r"((a)[2]), "r"((a)[3]), \
                   "r"((b)[0]), "r"((b)[1]))

// ---------------------------------------------------------------------------
// convert + transpose: src f32 [2][192][65536] -> dhi/dlo bf16 [2][65536][192]
// ---------------------------------------------------------------------------
__global__ __launch_bounds__(256) void convtrans(
    const float* __restrict__ src,
    unsigned short* __restrict__ dhi,
    unsigned short* __restrict__ dlo)
{
    __shared__ float sm[32][33];
    const int p0 = blockIdx.x * 32, c0 = blockIdx.y * 32, b = blockIdx.z;
    const float* s = src + (size_t)b * GK * NPIX;
    const int tc = threadIdx.x & 31, tr = threadIdx.x >> 5;

    #pragma unroll
    for (int i = 0; i < 4; i++) {
        int cl = tr + i * 8;
        sm[cl][tc] = s[(size_t)(c0 + cl) * NPIX + p0 + tc];
    }
    __syncthreads();

    const size_t obase = (size_t)b * NPIX * GK;
    #pragma unroll
    for (int i = 0; i < 4; i++) {
        int pl = tr + i * 8;
        float v = sm[tc][pl];
        __nv_bfloat16 h = __float2bfloat16(v);
        __nv_bfloat16 l = __float2bfloat16(v - __bfloat162float(h));
        size_t o = obase + (size_t)(p0 + pl) * GK + c0 + tc;
        dhi[o] = *(unsigned short*)&h;
        dlo[o] = *(unsigned short*)&l;
    }
}

__global__ void wconvert(const float* __restrict__ w, int n,
                         unsigned short* __restrict__ hi,
                         unsigned short* __restrict__ lo)
{
    int i = blockIdx.x * 256 + threadIdx.x;
    if (i < n) {
        float v = w[i];
        __nv_bfloat16 h = __float2bfloat16(v);
        __nv_bfloat16 l = __float2bfloat16(v - __bfloat162float(h));
        hi[i] = *(unsigned short*)&h;
        lo[i] = *(unsigned short*)&l;
    }
}

// ---------------------------------------------------------------------------
// mma.sync GEMM:  C[b,m,n] = sum_k A[m,k] * B[b,n,k]   (3-term bf16 split)
// CTA tile 64(M) x 128(N), 256 thr = 8 warps (2Mx4N), warp 32x32 via 2x4
// m16n8k16 tiles. K=192 in four 48-chunks, cp.async double-buffered.
// smem rows padded to 56 bf16 (112B): ldmatrix conflict-free.
// ---------------------------------------------------------------------------
__global__ __launch_bounds__(256) void gemm_mma(
    const unsigned short* __restrict__ Ahi,
    const unsigned short* __restrict__ Alo,
    const unsigned short* __restrict__ Bhi,
    const unsigned short* __restrict__ Blo,
    float* __restrict__ Cm, int Mtot)
{
    extern __shared__ __align__(16) unsigned short smem[];
    const int t = threadIdx.x, lane = t & 31, w = t >> 5;
    const int bM = blockIdx.x * 64;
    const size_t bN = (size_t)blockIdx.y * 128;
    const int batch = blockIdx.z;
    const int wm0 = (w >> 2) * 32;     // 0 / 32
    const int wn0 = (w & 3) * 32;      // 0 / 32 / 64 / 96

    const uint32_t sb = smem_u32(smem);
    // elem layout per buffer (21504 bf16 = 43008 B):
    //   A: [hl][64][56] at 0      (hl stride 3584)
    //   B: [hl][128][56] at 7168  (hl stride 7168)

    const unsigned short* gA[2] = { Ahi + (size_t)bM * GK, Alo + (size_t)bM * GK };
    const size_t boff = ((size_t)batch * NPIX + bN) * GK;
    const unsigned short* gB[2] = { Bhi + boff, Blo + boff };

    auto issue_chunk = [&](int c) {
        const uint32_t sbase = sb + (uint32_t)(c & 1) * 43008u;
        #pragma unroll
        for (int i = 0; i < 3; i++) {              // A: 2x64 rows x 6 chunks
            int id = t + i * 256;
            int hl = id / 384, rem = id - hl * 384;
            int row = rem / 6, c6 = rem - row * 6;
            uint32_t d = sbase + (uint32_t)(hl * 3584 + row * 56 + c6 * 8) * 2u;
            cp_async16(d, gA[hl] + row * GK + c * 48 + c6 * 8);
        }
        #pragma unroll
        for (int i = 0; i < 6; i++) {              // B: 2x128 rows x 6 chunks
            int id = t + i * 256;
            int hl = id / 768, rem = id - hl * 768;
            int row = rem / 6, c6 = rem - row * 6;
            uint32_t d = sbase + (uint32_t)(7168 + hl * 7168 + row * 56 + c6 * 8) * 2u;
            cp_async16(d, gB[hl] + row * GK + c * 48 + c6 * 8);
        }
        asm volatile("cp.async.commit_group;" ::: "memory");
    };

    float acc[2][4][4];
    #pragma unroll
    for (int mi = 0; mi < 2; mi++)
        #pragma unroll
        for (int ni = 0; ni < 4; ni++)
            #pragma unroll
            for (int r = 0; r < 4; r++) acc[mi][ni][r] = 0.f;

    // ldmatrix lane->address components
    const int arow = lane & 15;            // A: row within m16 tile
    const int akoff = (lane >> 4) * 8;     // A: k sub-block
    const int brow = lane & 7;             // B: n within n8 tile
    const int bkoff = ((lane >> 3) & 1) * 8;

    issue_chunk(0);
    #pragma unroll 1
    for (int c = 0; c < 4; c++) {
        if (c + 1 < 4) {
            issue_chunk(c + 1);
            asm volatile("cp.async.wait_group 1;" ::: "memory");
        } else {
            asm volatile("cp.async.wait_group 0;" ::: "memory");
        }
        __syncthreads();

        const uint32_t sbase = sb + (uint32_t)(c & 1) * 43008u;
        #pragma unroll
        for (int ks = 0; ks < 3; ks++) {
            const int k0 = ks * 16;
            uint32_t ah[2][4], al[2][4], bh[4][2], bl[4][2];
            #pragma unroll
            for (int mi = 0; mi < 2; mi++) {
                uint32_t off = (uint32_t)((wm0 + mi * 16 + arow) * 56 + k0 + akoff) * 2u;
                LDSM_X4(ah[mi][0], ah[mi][1], ah[mi][2], ah[mi][3], sbase + off);
                LDSM_X4(al[mi][0], al[mi][1], al[mi][2], al[mi][3],
                        sbase + 3584u * 2u + off);
            }
            #pragma unroll
            for (int ni = 0; ni < 4; ni++) {
                uint32_t off = (uint32_t)(7168 + (wn0 + ni * 8 + brow) * 56 + k0 + bkoff) * 2u;
                LDSM_X2(bh[ni][0], bh[ni][1], sbase + off);
                LDSM_X2(bl[ni][0], bl[ni][1], sbase + 7168u * 2u + off);
            }
            #pragma unroll
            for (int mi = 0; mi < 2; mi++)
                #pragma unroll
                for (int ni = 0; ni < 4; ni++) {
                    MMA16816(acc[mi][ni], ah[mi], bh[ni]);
                    MMA16816(acc[mi][ni], ah[mi], bl[ni]);
                    MMA16816(acc[mi][ni], al[mi], bh[ni]);
                }
        }
        __syncthreads();
    }

    // epilogue: direct STG.64 (8B per thread, 32B/quad-row, tiles adjacent)
    float* C = Cm + (size_t)batch * (size_t)Mtot * NPIX;
    const int mr = lane >> 2, nc = (lane & 3) * 2;
    #pragma unroll
    for (int mi = 0; mi < 2; mi++)
        #pragma unroll
        for (int ni = 0; ni < 4; ni++) {
            const size_t m = (size_t)(bM + wm0 + mi * 16 + mr);
            const size_t n = bN + wn0 + ni * 8 + nc;
            float* a = acc[mi][ni];
            *(float2*)&C[m * NPIX + n]       = make_float2(a[0], a[1]);
            *(float2*)&C[(m + 8) * NPIX + n] = make_float2(a[2], a[3]);
        }
}

// ---------------------------------------------------------------------------
// Fused depthwise-3x3 + 8x8-window channel attention (unchanged from R4).
// ---------------------------------------------------------------------------
__global__ __launch_bounds__(256) void window_attn(
    const float* __restrict__ dww,    // [576*9]
    const float* __restrict__ tempr)  // [4]
{
    const int t    = threadIdx.x;
    const int head = blockIdx.x & 3;
    const int win  = blockIdx.x >> 2;
    const int b    = win >> 10;
    const int hn   = (win >> 5) & 31;
    const int wn   = win & 31;
    const int y0   = hn << 3, x0 = wn << 3;

    __shared__ float sq[48 * 64];
    __shared__ float skT[64 * 52];
    __shared__ float sv[48 * 64];
    __shared__ float scratch[2400];
    __shared__ float qin[48], kin[48];

    const size_t qkv_base = (size_t)b * 576 * NPIX;

    float hreg[10];
    auto load_halo = [&](int gch0) {
        #pragma unroll
        for (int i = 0; i < 10; i++) {
            int e = t + i * 256;
            float v = 0.f;
            if (e < 2400) {
                int c  = e / 100;
                int px = e - c * 100;
                int iy = px / 10;
                int ix = px - iy * 10;
                int gy = y0 - 1 + iy;
                int gx = x0 - 1 + ix;
                if ((unsigned)gy < 256u && (unsigned)gx < 256u)
                    v = g_qkv[qkv_base + (size_t)(gch0 + c) * NPIX + gy * 256 + gx];
            }
            hreg[i] = v;
        }
    };

    load_halo(head * 48);
    #pragma unroll 1
    for (int p = 0; p < 6; p++) {
        const int tensor = p >> 1;
        const int half   = p & 1;
        const int gch0   = tensor * 192 + head * 48 + half * 24;

        #pragma unroll
        for (int i = 0; i < 10; i++) {
            int e = t + i * 256;
            if (e < 2400) scratch[e] = hreg[i];
        }
        __syncthreads();

        if (p < 5) {
            const int np = p + 1;
            load_halo((np >> 1) * 192 + head * 48 + (np & 1) * 24);
        }

        #pragma unroll
        for (int u = 0; u < 6; u++) {
            int e  = t + u * 256;
            int c  = e >> 6;
            int pp = e & 63;
            int p1 = pp >> 3, p2 = pp & 7;
            const float* wr = dww + (gch0 + c) * 9;
            const float* tp = scratch + c * 100 + p1 * 10 + p2;
            float s = tp[ 0]*wr[0] + tp[ 1]*wr[1] + tp[ 2]*wr[2]
                    + tp[10]*wr[3] + tp[11]*wr[4] + tp[12]*wr[5]
                    + tp[20]*wr[6] + tp[21]*wr[7] + tp[22]*wr[8];
            int ch = half * 24 + c;
            if      (tensor == 0) sq[ch * 64 + pp]  = s;
            else if (tensor == 1) skT[pp * 52 + ch] = s;
            else                  sv[ch * 64 + pp]  = s;
        }
        __syncthreads();
    }

    if (t < 48) {
        float s = 0.f;
        #pragma unroll 8
        for (int d = 0; d < 64; d++) {
            float x = sq[t * 64 + ((d + t) & 63)];
            s = fmaf(x, x, s);
        }
        qin[t] = 1.f / fmaxf(sqrtf(s), 1e-12f);
    } else if (t >= 128 && t < 176) {
        int j = t - 128;
        float s = 0.f;
        #pragma unroll 8
        for (int d = 0; d < 64; d++) {
            float x = skT[d * 52 + j];
            s = fmaf(x, x, s);
        }
        kin[j] = 1.f / fmaxf(sqrtf(s), 1e-12f);
    }
    __syncthreads();

    float* sattn = scratch;
    const float tscale = __ldg(&tempr[head]);

    {
        const int ti = t >> 4;
        const int tj = t & 15;
        const int i0 = ti * 3, j0 = tj * 3;
        float acc[3][3];
        #pragma unroll
        for (int r = 0; r < 3; r++)
            #pragma unroll
            for (int s = 0; s < 3; s++) acc[r][s] = 0.f;

        for (int d0 = 0; d0 < 64; d0 += 4) {
            float4 qv[3];
            #pragma unroll
            for (int r = 0; r < 3; r++)
                qv[r] = *(const float4*)&sq[(i0 + r) * 64 + d0];
            #pragma unroll
            for (int dd = 0; dd < 4; dd++) {
                float kv[3];
                #pragma unroll
                for (int s = 0; s < 3; s++) kv[s] = skT[(d0 + dd) * 52 + j0 + s];
                #pragma unroll
                for (int r = 0; r < 3; r++) {
                    float qd = (dd == 0) ? qv[r].x : (dd == 1) ? qv[r].y
                             : (dd == 2) ? qv[r].z : qv[r].w;
                    #pragma unroll
                    for (int s = 0; s < 3; s++)
                        acc[r][s] = fmaf(qd, kv[s], acc[r][s]);
                }
            }
        }
        #pragma unroll
        for (int r = 0; r < 3; r++) {
            float qi = qin[i0 + r] * tscale;
            #pragma unroll
            for (int s = 0; s < 3; s++)
                sattn[(i0 + r) * 49 + j0 + s] = acc[r][s] * qi * kin[j0 + s];
        }
    }
    __syncthreads();

    if (t < 48) {
        float m = -1e30f;
        #pragma unroll 8
        for (int j = 0; j < 48; j++) m = fmaxf(m, sattn[t * 49 + j]);
        float s = 0.f;
        #pragma unroll 8
        for (int j = 0; j < 48; j++) {
            float e = __expf(sattn[t * 49 + j] - m);
            sattn[t * 49 + j] = e;
            s += e;
        }
        float inv = 1.f / s;
        #pragma unroll 8
        for (int j = 0; j < 48; j++) sattn[t * 49 + j] *= inv;
    }
    __syncthreads();

    {
        const int td = t & 15;
        const int ti = t >> 4;
        const int d0 = td * 4, i0 = ti * 3;
        float acc[3][4];
        #pragma unroll
        for (int r = 0; r < 3; r++)
            #pragma unroll
            for (int s = 0; s < 4; s++) acc[r][s] = 0.f;

        for (int j = 0; j < 48; j++) {
            float4 vv = *(const float4*)&sv[j * 64 + d0];
            #pragma unroll
            for (int r = 0; r < 3; r++) {
                float a = sattn[(i0 + r) * 49 + j];
                acc[r][0] = fmaf(a, vv.x, acc[r][0]);
                acc[r][1] = fmaf(a, vv.y, acc[r][1]);
                acc[r][2] = fmaf(a, vv.z, acc[r][2]);
                acc[r][3] = fmaf(a, vv.w, acc[r][3]);
            }
        }
        const int p1 = d0 >> 3, p2 = d0 & 7;
        const size_t obase = (size_t)b * 192 * NPIX
                           + (size_t)(y0 + p1) * 256 + (x0 + p2);
        #pragma unroll
        for (int r = 0; r < 3; r++) {
            size_t off = obase + (size_t)(head * 48 + i0 + r) * NPIX;
            *(float4*)&g_att[off] = make_float4(acc[r][0], acc[r][1], acc[r][2], acc[r][3]);
        }
    }
}

// ---------------------------------------------------------------------------
extern "C" void kernel_launch(void* const* d_in, const int* in_sizes, int n_in,
                              void* d_out, int out_size)
{
    const float *x = nullptr, *qw = nullptr, *dw = nullptr, *pw = nullptr, *tp = nullptr;
    for (int i = 0; i < n_in; i++) {
        switch (in_sizes[i]) {
            case 25165824: x  = (const float*)d_in[i]; break;  // x [2,192,256,256]
            case 110592:   qw = (const float*)d_in[i]; break;  // qkv_w [576,192]
            case 5184:     dw = (const float*)d_in[i]; break;  // dw_w [576,1,3,3]
            case 36864:    pw = (const float*)d_in[i]; break;  // proj_w [192,192]
            case 4:        tp = (const float*)d_in[i]; break;  // temperature [4]
        }
    }

    void *qkvp, *attp, *bthp, *btlp, *wqhp, *wqlp, *wphp, *wplp;
    cudaGetSymbolAddress(&qkvp, g_qkv);
    cudaGetSymbolAddress(&attp, g_att);
    cudaGetSymbolAddress(&bthp, g_bth);
    cudaGetSymbolAddress(&btlp, g_btl);
    cudaGetSymbolAddress(&wqhp, g_wqh);
    cudaGetSymbolAddress(&wqlp, g_wql);
    cudaGetSymbolAddress(&wphp, g_wph);
    cudaGetSymbolAddress(&wplp, g_wpl);

    const int GEMM_SMEM = 2 * 43008;             // 86016 B
    cudaFuncSetAttribute(gemm_mma, cudaFuncAttributeMaxDynamicSharedMemorySize, GEMM_SMEM);

    // 0) weight splits (tiny)
    wconvert<<<(110592 + 255) / 256, 256>>>(qw, 110592,
        (unsigned short*)wqhp, (unsigned short*)wqlp);
    wconvert<<<(36864 + 255) / 256, 256>>>(pw, 36864,
        (unsigned short*)wphp, (unsigned short*)wplp);

    // 1) x -> x^T bf16 hi/lo
    convtrans<<<dim3(2048, 6, 2), 256>>>(x,
        (unsigned short*)bthp, (unsigned short*)btlp);

    // 2) qkv GEMM (tensor cores via mma.sync): [576,192] x [65536,192]^T
    gemm_mma<<<dim3(9, 512, 2), 256, GEMM_SMEM>>>(
        (const unsigned short*)wqhp, (const unsigned short*)wqlp,
        (const unsigned short*)bthp, (const unsigned short*)btlp,
        (float*)qkvp, 576);

    // 3) fused depthwise 3x3 + windowed channel attention (fp32)
    window_attn<<<8192, 256>>>(dw, tp);

    // 4) attn out -> transposed bf16 hi/lo (reuse buffers)
    convtrans<<<dim3(2048, 6, 2), 256>>>((const float*)attp,
        (unsigned short*)bthp, (unsigned short*)btlp);

    // 5) proj GEMM -> d_out
    gemm_mma<<<dim3(3, 512, 2), 256, GEMM_SMEM>>>(
        (const unsigned short*)wphp, (const unsigned short*)wplp,
        (const unsigned short*)bthp, (const unsigned short*)btlp,
        (float*)d_out, 192);
}